// round 4
// baseline (speedup 1.0000x reference)
#include <cuda_runtime.h>
#include <math.h>

#define SR_F        48000.0f
#define SOUND_SPEED 343.0f
#define MAX_ORDER   10
#define RIR_LEN     24000
#define TAPS        81
#define HALF        40
#define AXN         42            // axis-image table size (2*(2*10+1))
#define NVALID      1561          // #(ax,ay,az) triples with tot_order <= 10 (exact)
#define MAXB        16

// ---------------------------------------------------------------------------
// Compile-time table of valid axis-index triples (tot_order <= MAX_ORDER),
// packed as ax + 42*ay + 42*42*az. Batch-independent.
// ---------------------------------------------------------------------------
constexpr int axis_order_ct(int a) {
    int p = (a >= 21) ? 1 : 0;
    int n = a - 21 * p - 10;
    int o1 = n - p; if (o1 < 0) o1 = -o1;
    int o2 = n;     if (o2 < 0) o2 = -o2;
    return o1 + o2;
}

struct ValidTable {
    int v[NVALID];
    constexpr ValidTable() : v() {
        int ord[AXN] = {};
        for (int a = 0; a < AXN; ++a) ord[a] = axis_order_ct(a);
        int s = 0;
        for (int az = 0; az < AXN; ++az)
            for (int ay = 0; ay < AXN; ++ay)
                for (int ax = 0; ax < AXN; ++ax)
                    if (ord[ax] + ord[ay] + ord[az] <= MAX_ORDER)
                        v[s++] = ax + AXN * ay + AXN * AXN * az;
    }
};

__device__ const ValidTable VT = ValidTable();

// Per-(batch,image) record, 32B = two float4 loads.
struct Rec {
    int   base_g; // b*RIR_LEN + floor(tau) + HALF (== end_g if out of range)
    float frac;   // tau - floor(tau)
    float amp;    // beta^tot / (4*pi*dist)
    float c;      // amp * sin(pi*frac) / pi
    float cw;     // cos(pi*(40+frac)/41)
    float sw;     // sin(pi*(40+frac)/41)
    int   end_g;  // (b+1)*RIR_LEN
    float pad;
};

__device__ Rec                g_rec[MAXB * NVALID];
__device__ float2             g_tab[TAPS];   // {cos, sin}(pi*k/41)
__device__ unsigned long long g_bar;         // monotone generation barrier counter

__constant__ float BETA_POW[11] = {
    1.0f, 0.9f, 0.81f, 0.729f, 0.6561f, 0.59049f,
    0.531441f, 0.4782969f, 0.43046721f, 0.387420489f, 0.3486784401f
};

__device__ __forceinline__ void decode_axis(int a, float& sign, float& off, int& order)
{
    int p = (a >= 21) ? 1 : 0;
    int n = a - 21 * p - 10;
    sign  = (float)(1 - 2 * p);
    off   = (float)(2 * n);
    order = abs(n - p) + abs(n);
}

// Contribution of one tap: amp*sinc(t)*win(t), t = tap-40-frac.
__device__ __forceinline__ float tapval(int tap, float frac, float amp, float c,
                                        float cw, float sw)
{
    float t = (float)(tap - HALF) - frac;
    float v;
    if (t == 0.0f) v = amp;                                  // tap==40, frac==0
    else           v = __fdividef((tap & 1) ? c : -c, t);    // == amp*sinc(t)
    if (tap == 0 && frac > 0.0f) v = 0.0f;                   // |t| > HALF
    float2 cs = g_tab[tap];
    float win = 0.5f + 0.5f * fmaf(cs.x, cw, cs.y * sw);     // Hann window
    return v * win;
}

// ---------------------------------------------------------------------------
// Single fused persistent kernel.
// Phase 1: zero RIR, write origin, build tap table + records.
// Software grid barrier (generation counter; replay-safe, no reset needed).
// Phase 2: one warp per record; 16B-aligned red.global.add.v4.f32 scatter.
// d_out layout: [B*RIR_LEN floats rir][B floats origin]
// ---------------------------------------------------------------------------
__global__ void __launch_bounds__(256)
fused_kernel(const float* __restrict__ in, float* __restrict__ out,
             int B, int nrec, int zeroN4)
{
    const int nthreads = gridDim.x * blockDim.x;
    const int gtid = blockIdx.x * blockDim.x + threadIdx.x;

    // ---- Phase 1 ----
    for (int i = gtid; i < zeroN4; i += nthreads)
        ((float4*)out)[i] = make_float4(0.f, 0.f, 0.f, 0.f);

    if (gtid < TAPS) {
        float a = (float)gtid * (1.0f / 41.0f);
        g_tab[gtid] = make_float2(cospif(a), sinpif(a));
    }

    if (gtid < B) {
        const float* row = in + gtid * 9;
        float rx = row[0] * 10.0f, ry = row[1] * 10.0f, rz = row[2] * 10.0f;
        float dx = (row[3] - row[6]) * rx;
        float dy = (row[4] - row[7]) * ry;
        float dz = (row[5] - row[8]) * rz;
        out[B * RIR_LEN + gtid] =
            40.0f + SR_F * sqrtf(dx * dx + dy * dy + dz * dz) / SOUND_SPEED;
    }

    for (int i = gtid; i < nrec; i += nthreads) {
        int b = i / NVALID;
        int s = i - b * NVALID;
        int img = VT.v[s];

        int ax = img % AXN;
        int ay = (img / AXN) % AXN;
        int az = img / (AXN * AXN);

        float sgx, ofx; int ox; decode_axis(ax, sgx, ofx, ox);
        float sgy, ofy; int oy; decode_axis(ay, sgy, ofy, oy);
        float sgz, ofz; int oz; decode_axis(az, sgz, ofz, oz);

        const float* row = in + b * 9;
        float rx = row[0] * 10.0f, ry = row[1] * 10.0f, rz = row[2] * 10.0f;
        float mx = row[3] * rx,    my = row[4] * ry,    mz = row[5] * rz;
        float sx = row[6] * rx,    sy = row[7] * ry,    sz = row[8] * rz;

        float dx = sgx * sx + ofx * rx - mx;
        float dy = sgy * sy + ofy * ry - my;
        float dz = sgz * sz + ofz * rz - mz;

        float dist = sqrtf(dx * dx + dy * dy + dz * dz);
        float tau  = SR_F * dist / SOUND_SPEED;
        float i0   = floorf(tau);
        float frac = tau - i0;

        const float INV_PI = 0.318309886183790672f;
        Rec r;
        int base  = (int)i0 + HALF;
        int bofs  = b * RIR_LEN;
        r.end_g   = bofs + RIR_LEN;
        r.amp     = BETA_POW[ox + oy + oz] / (4.0f * 3.14159265358979323846f * dist);
        r.base_g  = (base >= RIR_LEN) ? r.end_g : bofs + base;
        r.frac    = frac;
        r.c       = r.amp * sinpif(frac) * INV_PI;
        float bb  = (40.0f + frac) * (1.0f / 41.0f);
        r.cw      = cospif(bb);
        r.sw      = sinpif(bb);
        r.pad     = 0.0f;
        g_rec[i]  = r;
    }

    // ---- Grid barrier (generation counter; all blocks are co-resident) ----
    __syncthreads();
    if (threadIdx.x == 0) {
        __threadfence();
        unsigned long long ticket = atomicAdd(&g_bar, 1ULL);
        unsigned long long gen_end =
            (ticket / gridDim.x + 1ULL) * (unsigned long long)gridDim.x;
        while (*(volatile unsigned long long*)&g_bar < gen_end) { }
        __threadfence();
    }
    __syncthreads();

    // ---- Phase 2: one warp per record ----
    const int warp   = gtid >> 5;
    const int nwarps = nthreads >> 5;
    const int lane   = gtid & 31;

    for (int r = warp; r < nrec; r += nwarps) {
        const float4* rp = (const float4*)&g_rec[r];
        float4 r0 = __ldg(rp + 0);     // broadcast
        float4 r1 = __ldg(rp + 1);
        int   base_g = __float_as_int(r0.x);
        float frac   = r0.y;
        float amp    = r0.z;
        float c      = r0.w;
        float cw     = r1.x;
        float sw     = r1.y;
        int   end_g  = __float_as_int(r1.z);

        int len = end_g - base_g;
        if (len <= 0) continue;
        if (len > TAPS) len = TAPS;

        int head = (4 - (base_g & 3)) & 3;
        if (head > len) head = len;
        int body = (len - head) >> 2;            // # of v4 chunks (<= 20)
        int tail = len - head - (body << 2);     // <= 3

        if (lane < body) {
            int tap0 = head + (lane << 2);
            float v0 = tapval(tap0 + 0, frac, amp, c, cw, sw);
            float v1 = tapval(tap0 + 1, frac, amp, c, cw, sw);
            float v2 = tapval(tap0 + 2, frac, amp, c, cw, sw);
            float v3 = tapval(tap0 + 3, frac, amp, c, cw, sw);
            float* addr = out + base_g + tap0;   // 16B aligned
            asm volatile("red.global.add.v4.f32 [%0], {%1, %2, %3, %4};"
                         :: "l"(addr), "f"(v0), "f"(v1), "f"(v2), "f"(v3)
                         : "memory");
        } else if (lane >= 20 && lane < 20 + head) {
            int tap = lane - 20;
            atomicAdd(out + base_g + tap, tapval(tap, frac, amp, c, cw, sw));
        } else if (lane >= 24 && lane < 24 + tail) {
            int tap = head + (body << 2) + (lane - 24);
            atomicAdd(out + base_g + tap, tapval(tap, frac, amp, c, cw, sw));
        }
    }
}

extern "C" void kernel_launch(void* const* d_in, const int* in_sizes, int n_in,
                              void* d_out, int out_size)
{
    const float* in = (const float*)d_in[0];
    float* out = (float*)d_out;
    int B = in_sizes[0] / 9;
    if (B > MAXB) B = MAXB;

    int dev = 0;
    cudaGetDevice(&dev);
    int sms = 148;
    cudaDeviceGetAttribute(&sms, cudaDevAttrMultiProcessorCount, dev);
    int nb = 0;
    cudaOccupancyMaxActiveBlocksPerMultiprocessor(&nb, fused_kernel, 256, 0);
    if (nb < 1) nb = 1;
    int grid = sms * nb;                 // guaranteed co-resident

    int nrec   = B * NVALID;
    int zeroN4 = B * (RIR_LEN / 4);
    fused_kernel<<<grid, 256>>>(in, out, B, nrec, zeroN4);
}

// round 5
// speedup vs baseline: 1.2005x; 1.2005x over previous
#include <cuda_runtime.h>
#include <math.h>

#define SR_F        48000.0f
#define SOUND_SPEED 343.0f
#define MAX_ORDER   10
#define RIR_LEN     24000
#define TAPS        81
#define HALF        40
#define AXN         42            // axis-image table size (2*(2*10+1))
#define NVALID      1561          // #(ax,ay,az) triples with tot_order <= 10 (exact)
#define MAXB        16

// ---------------------------------------------------------------------------
// Compile-time table of valid axis-index triples (tot_order <= MAX_ORDER),
// packed as ax + 42*ay + 42*42*az. Batch-independent.
// ---------------------------------------------------------------------------
constexpr int axis_order_ct(int a) {
    int p = (a >= 21) ? 1 : 0;
    int n = a - 21 * p - 10;
    int o1 = n - p; if (o1 < 0) o1 = -o1;
    int o2 = n;     if (o2 < 0) o2 = -o2;
    return o1 + o2;
}

struct ValidTable {
    int v[NVALID];
    constexpr ValidTable() : v() {
        int ord[AXN] = {};
        for (int a = 0; a < AXN; ++a) ord[a] = axis_order_ct(a);
        int s = 0;
        for (int az = 0; az < AXN; ++az)
            for (int ay = 0; ay < AXN; ++ay)
                for (int ax = 0; ax < AXN; ++ax)
                    if (ord[ax] + ord[ay] + ord[az] <= MAX_ORDER)
                        v[s++] = ax + AXN * ay + AXN * AXN * az;
    }
};

__device__ const ValidTable VT = ValidTable();

// Per-(batch,image) record, 32B = two float4 loads.
struct Rec {
    int   base_g; // b*RIR_LEN + floor(tau) + HALF (== end_g if out of range)
    float frac;   // tau - floor(tau)
    float amp;    // beta^tot / (4*pi*dist)
    float c;      // amp * sin(pi*frac) / pi
    float cw;     // cos(pi*(40+frac)/41)
    float sw;     // sin(pi*(40+frac)/41)
    int   end_g;  // (b+1)*RIR_LEN
    float pad;
};

__device__ Rec    g_rec[MAXB * NVALID];
__device__ float2 g_tab[TAPS];   // {cos, sin}(pi*k/41)

__constant__ float BETA_POW[11] = {
    1.0f, 0.9f, 0.81f, 0.729f, 0.6561f, 0.59049f,
    0.531441f, 0.4782969f, 0.43046721f, 0.387420489f, 0.3486784401f
};

__device__ __forceinline__ void decode_axis(int a, float& sign, float& off, int& order)
{
    int p = (a >= 21) ? 1 : 0;
    int n = a - 21 * p - 10;
    sign  = (float)(1 - 2 * p);
    off   = (float)(2 * n);
    order = abs(n - p) + abs(n);
}

// Contribution of one tap: amp*sinc(t)*win(t), t = tap-40-frac.
__device__ __forceinline__ float tapval(int tap, float frac, float amp, float c,
                                        float cw, float sw)
{
    float t = (float)(tap - HALF) - frac;
    float v;
    if (t == 0.0f) v = amp;                                  // tap==40, frac==0
    else           v = __fdividef((tap & 1) ? c : -c, t);    // == amp*sinc(t)
    if (tap == 0 && frac > 0.0f) v = 0.0f;                   // |t| > HALF
    float2 cs = g_tab[tap];
    float win = 0.5f + 0.5f * fmaf(cs.x, cw, cs.y * sw);     // Hann window
    return v * win;
}

// ---------------------------------------------------------------------------
// Kernel A: zero RIR (float4), build records from compile-time table,
// tap cos/sin table, origin.
// d_out layout: [B*RIR_LEN floats rir][B floats origin]
// ---------------------------------------------------------------------------
__global__ void __launch_bounds__(256)
prep_kernel(const float* __restrict__ in, float* __restrict__ out,
            int B, int zeroN4, int nrec)
{
    int i = blockIdx.x * blockDim.x + threadIdx.x;

    if (i < zeroN4)
        ((float4*)out)[i] = make_float4(0.f, 0.f, 0.f, 0.f);

    if (i < TAPS) {
        float a = (float)i * (1.0f / 41.0f);
        g_tab[i] = make_float2(cospif(a), sinpif(a));
    }

    if (i < B) {
        const float* row = in + i * 9;
        float rx = row[0] * 10.0f, ry = row[1] * 10.0f, rz = row[2] * 10.0f;
        float dx = (row[3] - row[6]) * rx;
        float dy = (row[4] - row[7]) * ry;
        float dz = (row[5] - row[8]) * rz;
        out[B * RIR_LEN + i] =
            40.0f + SR_F * sqrtf(dx * dx + dy * dy + dz * dz) / SOUND_SPEED;
    }

    if (i < nrec) {
        int b = i / NVALID;
        int s = i - b * NVALID;
        int img = VT.v[s];

        int ax = img % AXN;
        int ay = (img / AXN) % AXN;
        int az = img / (AXN * AXN);

        float sgx, ofx; int ox; decode_axis(ax, sgx, ofx, ox);
        float sgy, ofy; int oy; decode_axis(ay, sgy, ofy, oy);
        float sgz, ofz; int oz; decode_axis(az, sgz, ofz, oz);

        const float* row = in + b * 9;
        float rx = row[0] * 10.0f, ry = row[1] * 10.0f, rz = row[2] * 10.0f;
        float mx = row[3] * rx,    my = row[4] * ry,    mz = row[5] * rz;
        float sx = row[6] * rx,    sy = row[7] * ry,    sz = row[8] * rz;

        float dx = sgx * sx + ofx * rx - mx;
        float dy = sgy * sy + ofy * ry - my;
        float dz = sgz * sz + ofz * rz - mz;

        float dist = sqrtf(dx * dx + dy * dy + dz * dz);
        float tau  = SR_F * dist / SOUND_SPEED;
        float i0   = floorf(tau);
        float frac = tau - i0;

        const float INV_PI = 0.318309886183790672f;
        Rec r;
        int base  = (int)i0 + HALF;
        int bofs  = b * RIR_LEN;
        r.end_g   = bofs + RIR_LEN;
        r.amp     = BETA_POW[ox + oy + oz] / (4.0f * 3.14159265358979323846f * dist);
        r.base_g  = (base >= RIR_LEN) ? r.end_g : bofs + base;
        r.frac    = frac;
        r.c       = r.amp * sinpif(frac) * INV_PI;
        float bb  = (40.0f + frac) * (1.0f / 41.0f);
        r.cw      = cospif(bb);
        r.sw      = sinpif(bb);
        r.pad     = 0.0f;
        g_rec[i]  = r;
    }
}

// ---------------------------------------------------------------------------
// Kernel B: one warp per record.
// Lanes 0..body-1: 16B-aligned red.global.add.v4.f32 (4 taps each).
// Lanes 20..22: head scalars; lanes 24..26: tail scalars.
// ---------------------------------------------------------------------------
__global__ void __launch_bounds__(256)
tap_kernel(float* __restrict__ out, int nrec)
{
    int w    = (blockIdx.x * blockDim.x + threadIdx.x) >> 5;
    int lane = threadIdx.x & 31;
    if (w >= nrec) return;

    const float4* rp = (const float4*)&g_rec[w];
    float4 r0 = __ldg(rp + 0);       // broadcast: all lanes same address
    float4 r1 = __ldg(rp + 1);
    int   base_g = __float_as_int(r0.x);
    float frac   = r0.y;
    float amp    = r0.z;
    float c      = r0.w;
    float cw     = r1.x;
    float sw     = r1.y;
    int   end_g  = __float_as_int(r1.z);

    int len = end_g - base_g;
    if (len <= 0) return;
    if (len > TAPS) len = TAPS;

    int head = (4 - (base_g & 3)) & 3;
    if (head > len) head = len;
    int body = (len - head) >> 2;            // # of v4 chunks (<= 20)
    int tail = len - head - (body << 2);     // <= 3

    if (lane < body) {
        int tap0 = head + (lane << 2);
        float v0 = tapval(tap0 + 0, frac, amp, c, cw, sw);
        float v1 = tapval(tap0 + 1, frac, amp, c, cw, sw);
        float v2 = tapval(tap0 + 2, frac, amp, c, cw, sw);
        float v3 = tapval(tap0 + 3, frac, amp, c, cw, sw);
        float* addr = out + base_g + tap0;   // 16B aligned
        asm volatile("red.global.add.v4.f32 [%0], {%1, %2, %3, %4};"
                     :: "l"(addr), "f"(v0), "f"(v1), "f"(v2), "f"(v3)
                     : "memory");
    } else if (lane >= 20 && lane < 20 + head) {
        int tap = lane - 20;
        atomicAdd(out + base_g + tap, tapval(tap, frac, amp, c, cw, sw));
    } else if (lane >= 24 && lane < 24 + tail) {
        int tap = head + (body << 2) + (lane - 24);
        atomicAdd(out + base_g + tap, tapval(tap, frac, amp, c, cw, sw));
    }
}

extern "C" void kernel_launch(void* const* d_in, const int* in_sizes, int n_in,
                              void* d_out, int out_size)
{
    const float* in = (const float*)d_in[0];
    float* out = (float*)d_out;
    int B = in_sizes[0] / 9;
    if (B > MAXB) B = MAXB;

    int nrec   = B * NVALID;
    int zeroN4 = B * (RIR_LEN / 4);              // float4 count (RIR_LEN % 4 == 0)
    int threadsA = zeroN4;                        // zeroN4 >= nrec, TAPS, B always
    prep_kernel<<<(threadsA + 255) / 256, 256>>>(in, out, B, zeroN4, nrec);

    int threadsB = nrec * 32;                     // one warp per record
    tap_kernel<<<(threadsB + 255) / 256, 256>>>(out, nrec);
}